// round 14
// baseline (speedup 1.0000x reference)
#include <cuda_runtime.h>
#include <cstdint>
#include <math.h>

#define BATCH 32768
#define DIM   1024
#define HID   256

// ---------------- device scratch (no runtime allocation) -------------------
__device__ int8_t g_Fd0[(size_t)BATCH * DIM];   // 32 MB each
__device__ int8_t g_Fd1[(size_t)BATCH * DIM];
__device__ int8_t g_Fd2[(size_t)BATCH * DIM];
__device__ int8_t g_Fd3[(size_t)BATCH * DIM];
__device__ float  g_qF[BATCH];                   // per-row scale 2^(e-29)
__device__ float  g_H[(size_t)BATCH * HID];      // 32 MB fp32
__device__ int8_t g_Hd0[(size_t)BATCH * HID];
__device__ int8_t g_Hd1[(size_t)BATCH * HID];
__device__ int8_t g_Hd2[(size_t)BATCH * HID];
__device__ int8_t g_Hd3[(size_t)BATCH * HID];
__device__ float  g_qH[BATCH];
__device__ int8_t g_W1d0[HID * DIM], g_W1d1[HID * DIM];   // [N=256][K=1024]
__device__ int8_t g_W1d2[HID * DIM], g_W1d3[HID * DIM];
__device__ float  g_qW1[HID];
__device__ int8_t g_W2d0[DIM * HID], g_W2d1[DIM * HID];   // [N=1024][K=256]
__device__ int8_t g_W2d2[DIM * HID], g_W2d3[DIM * HID];
__device__ float  g_qW2[DIM];
__device__ float  g_comp[(size_t)BATCH * DIM];   // 128 MB

__device__ __forceinline__ float sigmoidf_(float x) {
    return 1.0f / (1.0f + expf(-x));
}

// exact 4-digit s8 decomposition of v (|v| < 2^30):
//   v = d0*2^24 + d1*2^16 + d2*2^8 + d3,  |d0| <= 64
__device__ __forceinline__ void digits4(int v, int& d0, int& d1, int& d2, int& d3) {
    d3 = (v << 24) >> 24;
    int v1 = (v - d3) >> 8;
    d2 = (v1 << 24) >> 24;
    int v2 = (v1 - d2) >> 8;
    d1 = (v2 << 24) >> 24;
    d0 = (v2 - d1) >> 8;
}

__device__ __forceinline__ void cp16(void* s, const void* gp) {
    uint32_t sa = (uint32_t)__cvta_generic_to_shared(s);
    asm volatile("cp.async.cg.shared.global [%0], [%1], 16;\n" :: "r"(sa), "l"(gp));
}
#define CP_COMMIT() asm volatile("cp.async.commit_group;\n")
#define CP_WAIT1()  asm volatile("cp.async.wait_group 1;\n")
#define CP_WAIT0()  asm volatile("cp.async.wait_group 0;\n")

// int8 IMMA, exact int32 D-chain accumulate
__device__ __forceinline__ void imma(int* d, const uint32_t* a, const uint32_t* b) {
    asm volatile(
        "mma.sync.aligned.m16n8k32.row.col.s32.s8.s8.s32 "
        "{%0,%1,%2,%3}, {%4,%5,%6,%7}, {%8,%9}, {%0,%1,%2,%3};\n"
        : "+r"(d[0]), "+r"(d[1]), "+r"(d[2]), "+r"(d[3])
        : "r"(a[0]), "r"(a[1]), "r"(a[2]), "r"(a[3]), "r"(b[0]), "r"(b[1]));
}

__device__ __forceinline__ void ldsm4(uint32_t* r, const void* p) {
    uint32_t a = (uint32_t)__cvta_generic_to_shared(p);
    asm volatile("ldmatrix.sync.aligned.m8n8.x4.shared.b16 {%0,%1,%2,%3}, [%4];"
        : "=r"(r[0]), "=r"(r[1]), "=r"(r[2]), "=r"(r[3]) : "r"(a));
}

// ---------------- quantization kernels --------------------------------------
// F rows (K=1024): one CTA per row, 4 elements/thread
__global__ __launch_bounds__(256) void quant_f_k(const float* __restrict__ x) {
    __shared__ float sm[8];
    const int row = blockIdx.x, tid = threadIdx.x, lane = tid & 31, wid = tid >> 5;
    float4 v = *(const float4*)(x + (size_t)row * DIM + tid * 4);
    float m = fmaxf(fmaxf(fabsf(v.x), fabsf(v.y)), fmaxf(fabsf(v.z), fabsf(v.w)));
#pragma unroll
    for (int o = 16; o; o >>= 1) m = fmaxf(m, __shfl_xor_sync(0xffffffffu, m, o));
    if (lane == 0) sm[wid] = m;
    __syncthreads();
    m = sm[0];
#pragma unroll
    for (int w = 1; w < 8; w++) m = fmaxf(m, sm[w]);
    m = fmaxf(m, 1e-30f);
    int e = ilogbf(m);
    float scale = exp2f((float)(29 - e));
    if (tid == 0) g_qF[row] = exp2f((float)(e - 29));
    float av[4] = { v.x, v.y, v.z, v.w };
    char c0[4], c1[4], c2[4], c3[4];
#pragma unroll
    for (int j = 0; j < 4; j++) {
        int vi = __float2int_rn(av[j] * scale);
        int d0, d1, d2, d3;
        digits4(vi, d0, d1, d2, d3);
        c0[j] = (char)d0; c1[j] = (char)d1; c2[j] = (char)d2; c3[j] = (char)d3;
    }
    size_t o = (size_t)row * DIM + tid * 4;
    *(char4*)(g_Fd0 + o) = make_char4(c0[0], c0[1], c0[2], c0[3]);
    *(char4*)(g_Fd1 + o) = make_char4(c1[0], c1[1], c1[2], c1[3]);
    *(char4*)(g_Fd2 + o) = make_char4(c2[0], c2[1], c2[2], c2[3]);
    *(char4*)(g_Fd3 + o) = make_char4(c3[0], c3[1], c3[2], c3[3]);
}

// H rows (K=256): one CTA per row, 1 element/thread
__global__ __launch_bounds__(256) void quant_h_k(void) {
    __shared__ float sm[8];
    const int row = blockIdx.x, tid = threadIdx.x, lane = tid & 31, wid = tid >> 5;
    float a = g_H[(size_t)row * HID + tid];
    float m = fabsf(a);
#pragma unroll
    for (int o = 16; o; o >>= 1) m = fmaxf(m, __shfl_xor_sync(0xffffffffu, m, o));
    if (lane == 0) sm[wid] = m;
    __syncthreads();
    m = sm[0];
#pragma unroll
    for (int w = 1; w < 8; w++) m = fmaxf(m, sm[w]);
    m = fmaxf(m, 1e-30f);
    int e = ilogbf(m);
    float scale = exp2f((float)(29 - e));
    if (tid == 0) g_qH[row] = exp2f((float)(e - 29));
    int vi = __float2int_rn(a * scale);
    int d0, d1, d2, d3;
    digits4(vi, d0, d1, d2, d3);
    size_t o = (size_t)row * HID + tid;
    g_Hd0[o] = (char)d0; g_Hd1[o] = (char)d1;
    g_Hd2[o] = (char)d2; g_Hd3[o] = (char)d3;
}

// W cols: w[K][N] -> transposed digit planes [N][K]; one thread per column
__global__ __launch_bounds__(256) void quant_w_k(const float* __restrict__ w,
                                                 int8_t* __restrict__ p0,
                                                 int8_t* __restrict__ p1,
                                                 int8_t* __restrict__ p2,
                                                 int8_t* __restrict__ p3,
                                                 float* __restrict__ qcol,
                                                 int K, int N) {
    int c = blockIdx.x * 256 + threadIdx.x;
    if (c >= N) return;
    float m = 1e-30f;
    for (int k = 0; k < K; k++) m = fmaxf(m, fabsf(w[(size_t)k * N + c]));
    int e = ilogbf(m);
    float scale = exp2f((float)(29 - e));
    qcol[c] = exp2f((float)(e - 29));
    for (int k = 0; k < K; k++) {
        int vi = __float2int_rn(w[(size_t)k * N + c] * scale);
        int d0, d1, d2, d3;
        digits4(vi, d0, d1, d2, d3);
        size_t o = (size_t)c * K + k;
        p0[o] = (char)d0; p1[o] = (char)d1; p2[o] = (char)d2; p3[o] = (char)d3;
    }
}

// ---------------- int8 4-digit GEMM ------------------------------------------
// x = qa[m]*qb[n]*2^24*(S0*2^24 + S1*2^16 + S2*2^8 + S3) + bias
// Sg = exact int32 sums of digit products with i+j==g (groups 0..3 kept;
// dropped i+j>=4 terms are ~3e-8 relative). Int32 D-chains are exact ->
// no truncation, no extraction FADDs, chained across all of K.
// CTA 64x64, BK=32, 8 warps as 2(M)x4(N), warp tile 32x16 (mt=2, nt=2).
// EPI==0: g_H = relu(x)                 (A=F digits, K=1024, N=256)
// EPI==1: g_comp = thresh(F*sigmoid(x)) (A=H digits, K=256,  N=1024)
//   (reference "competition" branch is dead code: win == False always)
#define BM 64
#define BN 64
#define BK 32
#define ROWB 48                               // bytes per smem row (32 + 16 pad)
#define NSTAGE 3
#define STAGE_BYTES (4 * (BM + BN) * ROWB)    // 24576 B per stage
#define SMEM_BYTES  (NSTAGE * STAGE_BYTES)    // 73728 B

template <int EPI, int K, int N>
__global__ __launch_bounds__(256, 2) void gemm_i8(
    const int8_t* __restrict__ A0g, const int8_t* __restrict__ A1g,
    const int8_t* __restrict__ A2g, const int8_t* __restrict__ A3g,
    const int8_t* __restrict__ B0g, const int8_t* __restrict__ B1g,
    const int8_t* __restrict__ B2g, const int8_t* __restrict__ B3g,
    const float* __restrict__ qa, const float* __restrict__ qb,
    const float* __restrict__ bias,
    const float* __restrict__ F)
{
    constexpr int KT = K / BK;
    extern __shared__ __align__(16) char smem[];
#define ASP_(st,p,r) (smem + (st) * STAGE_BYTES + ((p) * BM + (r)) * ROWB)
#define BSP_(st,p,r) (smem + (st) * STAGE_BYTES + 4 * BM * ROWB + ((p) * BN + (r)) * ROWB)

    const int tid  = threadIdx.x;
    const int lane = tid & 31;
    const int wid  = tid >> 5;
    const int gq   = lane >> 2;
    const int t    = lane & 3;
    const int mW   = (wid & 1) * 32;    // warp M offset
    const int nW   = (wid >> 1) * 16;   // warp N offset

    const int aRowL = (lane & 7) + ((lane >> 3) & 1) * 8;
    const int aByteL = ((lane >> 4) & 1) * 16;
    const int bRowL = nW + ((lane >> 4) & 1) * 8 + (lane & 7);
    const int bByteL = ((lane >> 3) & 1) * 16;

    const size_t mBase = (size_t)blockIdx.y * BM;
    const int    nBase = blockIdx.x * BN;

    const int8_t* Ap[4] = { A0g + mBase * K, A1g + mBase * K,
                            A2g + mBase * K, A3g + mBase * K };
    const int8_t* Bp[4] = { B0g + (size_t)nBase * K, B1g + (size_t)nBase * K,
                            B2g + (size_t)nBase * K, B3g + (size_t)nBase * K };

    int acc[2][2][4][4];   // [mt][nt][group][quad]
#pragma unroll
    for (int mt = 0; mt < 2; mt++)
#pragma unroll
        for (int nt = 0; nt < 2; nt++)
#pragma unroll
            for (int g = 0; g < 4; g++)
#pragma unroll
                for (int q = 0; q < 4; q++) acc[mt][nt][g][q] = 0;

    auto load_stage = [&](int kt, int st) {
        // A: 4 planes x 64 rows x 2 halves = 512; B same; 4 cp16/thread
#pragma unroll
        for (int u = 0; u < 2; u++) {
            int l = tid + u * 256;
            int p = l >> 7, rr = (l & 127) >> 1, h = l & 1;
            cp16(ASP_(st, p, rr) + h * 16, Ap[p] + (size_t)rr * K + kt * BK + h * 16);
        }
#pragma unroll
        for (int u = 0; u < 2; u++) {
            int l = tid + u * 256;
            int p = l >> 7, rr = (l & 127) >> 1, h = l & 1;
            cp16(BSP_(st, p, rr) + h * 16, Bp[p] + (size_t)rr * K + kt * BK + h * 16);
        }
    };

    load_stage(0, 0);
    CP_COMMIT();
    if (KT > 1) { load_stage(1, 1); CP_COMMIT(); }
    CP_WAIT1();
    __syncthreads();

    for (int kt = 0; kt < KT; kt++) {
        const int st = kt % NSTAGE;
        if (kt + 2 < KT) { load_stage(kt + 2, (kt + 2) % NSTAGE); CP_COMMIT(); }

        // B fragments: 4 planes, x4 covers both nt and both k-halves
        uint32_t bfr[4][4];
#pragma unroll
        for (int p = 0; p < 4; p++)
            ldsm4(bfr[p], BSP_(st, p, bRowL) + bByteL);

#pragma unroll
        for (int mt = 0; mt < 2; mt++) {
            uint32_t afr[4][4];
#pragma unroll
            for (int p = 0; p < 4; p++)
                ldsm4(afr[p], ASP_(st, p, mW + mt * 16 + aRowL) + aByteL);
#pragma unroll
            for (int nt = 0; nt < 2; nt++) {
                const uint32_t b0[2] = { bfr[0][nt * 2], bfr[0][nt * 2 + 1] };
                const uint32_t b1[2] = { bfr[1][nt * 2], bfr[1][nt * 2 + 1] };
                const uint32_t b2[2] = { bfr[2][nt * 2], bfr[2][nt * 2 + 1] };
                const uint32_t b3[2] = { bfr[3][nt * 2], bfr[3][nt * 2 + 1] };
                imma(acc[mt][nt][0], afr[0], b0);   // g0: 00
                imma(acc[mt][nt][1], afr[0], b1);   // g1: 01
                imma(acc[mt][nt][1], afr[1], b0);   //     10
                imma(acc[mt][nt][2], afr[0], b2);   // g2: 02
                imma(acc[mt][nt][2], afr[1], b1);   //     11
                imma(acc[mt][nt][2], afr[2], b0);   //     20
                imma(acc[mt][nt][3], afr[0], b3);   // g3: 03
                imma(acc[mt][nt][3], afr[1], b2);   //     12
                imma(acc[mt][nt][3], afr[2], b1);   //     21
                imma(acc[mt][nt][3], afr[3], b0);   //     30
            }
        }

        if (kt + 1 < KT) {
            if (kt + 2 < KT) CP_WAIT1();
            else             CP_WAIT0();
            __syncthreads();
        }
    }

    // epilogue: x = qa*qb*2^24*(S0*2^24 + S1*2^16 + S2*2^8 + S3) + bias
#pragma unroll
    for (int mt = 0; mt < 2; mt++) {
#pragma unroll
        for (int nt = 0; nt < 2; nt++) {
            size_t r0 = mBase + mW + mt * 16 + gq;
            size_t r1 = r0 + 8;
            int c = nBase + nW + nt * 8 + 2 * t;
            float qb0 = __ldg(qb + c) * 16777216.0f;
            float qb1 = __ldg(qb + c + 1) * 16777216.0f;
            float qa0 = __ldg(qa + r0), qa1 = __ldg(qa + r1);
            float b0 = __ldg(bias + c), b1 = __ldg(bias + c + 1);
            float xv[4];
#pragma unroll
            for (int q = 0; q < 4; q++) {
                float s = (float)acc[mt][nt][0][q] * 16777216.0f
                        + (float)acc[mt][nt][1][q] * 65536.0f
                        + (float)acc[mt][nt][2][q] * 256.0f
                        + (float)acc[mt][nt][3][q];
                float qq = ((q < 2) ? qa0 : qa1) * ((q & 1) ? qb1 : qb0);
                xv[q] = s * qq + ((q & 1) ? b1 : b0);
            }
            if (EPI == 0) {
                float2 h0 = { fmaxf(xv[0], 0.f), fmaxf(xv[1], 0.f) };
                float2 h1 = { fmaxf(xv[2], 0.f), fmaxf(xv[3], 0.f) };
                *(float2*)(g_H + r0 * N + c) = h0;
                *(float2*)(g_H + r1 * N + c) = h1;
            } else {
                float2 f0 = *(const float2*)(F + r0 * N + c);
                float2 f1 = *(const float2*)(F + r1 * N + c);
                float g00 = f0.x * sigmoidf_(xv[0]), g01 = f0.y * sigmoidf_(xv[1]);
                float g10 = f1.x * sigmoidf_(xv[2]), g11 = f1.y * sigmoidf_(xv[3]);
                float2 o0, o1;
                o0.x = (g00 > 0.3f) ? 0.f : g00;  o0.y = (g01 > 0.3f) ? 0.f : g01;
                o1.x = (g10 > 0.3f) ? 0.f : g10;  o1.y = (g11 > 0.3f) ? 0.f : g11;
                *(float2*)(g_comp + r0 * N + c) = o0;
                *(float2*)(g_comp + r1 * N + c) = o1;
            }
        }
    }
#undef ASP_
#undef BSP_
}

// ---------------- row-wise post-processing ----------------------------------
#define R3 8

__global__ __launch_bounds__(256) void rowpost_k(
    const float* __restrict__ w_r1, const float* __restrict__ b_r1,
    const float* __restrict__ w_r2, const float* __restrict__ b_r2,
    const float* __restrict__ w_m1, const float* __restrict__ b_m1,
    const float* __restrict__ w_m2, const float* __restrict__ b_m2,
    float* __restrict__ out)
{
    const int tid  = threadIdx.x;
    const int lane = tid & 31;
    const int wid  = tid >> 5;

    __shared__ float sA[8], sB[8], sC[8], sD[8];

    float wr2[16][4];
#pragma unroll
    for (int k = 0; k < 16; k++)
#pragma unroll
        for (int j = 0; j < 4; j++)
            wr2[k][j] = __ldg(w_r2 + k * DIM + tid + 256 * j);
    float br2r[4];
#pragma unroll
    for (int j = 0; j < 4; j++) br2r[j] = __ldg(b_r2 + tid + 256 * j);

    for (int rr = 0; rr < R3; rr++) {
        size_t row = (size_t)blockIdx.x * R3 + rr;
        const float* cr = g_comp + row * DIM;

        __syncthreads();

        float v[4];
#pragma unroll
        for (int j = 0; j < 4; j++) v[j] = cr[tid + 256 * j];

        float cnt = 0.0f;
#pragma unroll
        for (int j = 0; j < 4; j++) cnt += (fabsf(v[j]) < 0.1f) ? 1.0f : 0.0f;
#pragma unroll
        for (int o = 16; o; o >>= 1) cnt += __shfl_xor_sync(0xffffffffu, cnt, o);
        if (lane == 0) sD[wid] = cnt;
        __syncthreads();
        cnt = 0.0f;
#pragma unroll
        for (int w = 0; w < 8; w++) cnt += sD[w];
        float cur_sp = cnt * (1.0f / 1024.0f);

        float hr[16];
#pragma unroll
        for (int k = 0; k < 16; k++) {
            float x = fmaf(cur_sp, __ldg(w_r1 + k),
                      fmaf(0.1f, __ldg(w_r1 + 16 + k), __ldg(b_r1 + k)));
            hr[k] = fmaxf(x, 0.0f);
        }

        float dyn[4];
        float s1 = 0.0f, s2 = 0.0f, mx = -INFINITY;
#pragma unroll
        for (int j = 0; j < 4; j++) {
            float a = br2r[j];
#pragma unroll
            for (int k = 0; k < 16; k++) a = fmaf(hr[k], wr2[k][j], a);
            float rw = sigmoidf_(a);
            float d  = v[j] * rw;
            dyn[j] = d;
            s1 += d;
            s2 = fmaf(d, d, s2);
            mx = fmaxf(mx, d);
        }
#pragma unroll
        for (int o = 16; o; o >>= 1) {
            s1 += __shfl_xor_sync(0xffffffffu, s1, o);
            s2 += __shfl_xor_sync(0xffffffffu, s2, o);
            mx = fmaxf(mx, __shfl_xor_sync(0xffffffffu, mx, o));
        }
        if (lane == 0) { sA[wid] = s1; sB[wid] = s2; sC[wid] = mx; }
        __syncthreads();
        s1 = 0.0f; s2 = 0.0f; mx = -INFINITY;
#pragma unroll
        for (int w = 0; w < 8; w++) {
            s1 += sA[w]; s2 += sB[w]; mx = fmaxf(mx, sC[w]);
        }

        float fmean = s1 * (1.0f / 1024.0f);
        float var   = (s2 - s1 * fmean) * (1.0f / 1023.0f);   // ddof=1
        var = fmaxf(var, 0.0f);
        float fstd = sqrtf(var);

        float a2 = __ldg(b_m2);
#pragma unroll
        for (int k = 0; k < 16; k++) {
            float x = fmaf(fmean, __ldg(w_m1 + k),
                      fmaf(fstd, __ldg(w_m1 + 16 + k),
                      fmaf(mx,   __ldg(w_m1 + 32 + k), __ldg(b_m1 + k))));
            a2 = fmaf(fmaxf(x, 0.0f), __ldg(w_m2 + k), a2);
        }
        float thr = sigmoidf_(a2);

        float* orow = out + row * DIM;
#pragma unroll
        for (int j = 0; j < 4; j++)
            orow[tid + 256 * j] = (fabsf(dyn[j]) > thr) ? dyn[j] : 0.0f;
    }
}

// ---------------- launch -----------------------------------------------------
extern "C" void kernel_launch(void* const* d_in, const int* in_sizes, int n_in,
                              void* d_out, int out_size)
{
    const float* F   = (const float*)d_in[0];
    const float* wg1 = (const float*)d_in[1];
    const float* bg1 = (const float*)d_in[2];
    const float* wg2 = (const float*)d_in[3];
    const float* bg2 = (const float*)d_in[4];
    // d_in[5..8] = competition weights: dead code (win == False always)
    const float* wr1 = (const float*)d_in[9];
    const float* br1 = (const float*)d_in[10];
    const float* wr2 = (const float*)d_in[11];
    const float* br2 = (const float*)d_in[12];
    const float* wm1 = (const float*)d_in[13];
    const float* bm1 = (const float*)d_in[14];
    const float* wm2 = (const float*)d_in[15];
    const float* bm2 = (const float*)d_in[16];
    float* out = (float*)d_out;
    (void)in_sizes; (void)n_in; (void)out_size;

    int8_t *Fd0, *Fd1, *Fd2, *Fd3, *Hd0, *Hd1, *Hd2, *Hd3;
    int8_t *W1d0, *W1d1, *W1d2, *W1d3, *W2d0, *W2d1, *W2d2, *W2d3;
    float *qF, *qH, *qW1, *qW2;
    cudaGetSymbolAddress((void**)&Fd0, g_Fd0);
    cudaGetSymbolAddress((void**)&Fd1, g_Fd1);
    cudaGetSymbolAddress((void**)&Fd2, g_Fd2);
    cudaGetSymbolAddress((void**)&Fd3, g_Fd3);
    cudaGetSymbolAddress((void**)&Hd0, g_Hd0);
    cudaGetSymbolAddress((void**)&Hd1, g_Hd1);
    cudaGetSymbolAddress((void**)&Hd2, g_Hd2);
    cudaGetSymbolAddress((void**)&Hd3, g_Hd3);
    cudaGetSymbolAddress((void**)&W1d0, g_W1d0);
    cudaGetSymbolAddress((void**)&W1d1, g_W1d1);
    cudaGetSymbolAddress((void**)&W1d2, g_W1d2);
    cudaGetSymbolAddress((void**)&W1d3, g_W1d3);
    cudaGetSymbolAddress((void**)&W2d0, g_W2d0);
    cudaGetSymbolAddress((void**)&W2d1, g_W2d1);
    cudaGetSymbolAddress((void**)&W2d2, g_W2d2);
    cudaGetSymbolAddress((void**)&W2d3, g_W2d3);
    cudaGetSymbolAddress((void**)&qF, g_qF);
    cudaGetSymbolAddress((void**)&qH, g_qH);
    cudaGetSymbolAddress((void**)&qW1, g_qW1);
    cudaGetSymbolAddress((void**)&qW2, g_qW2);

    static int attr_done = 0;
    if (!attr_done) {
        cudaFuncSetAttribute(gemm_i8<0, DIM, HID>,
                             cudaFuncAttributeMaxDynamicSharedMemorySize, SMEM_BYTES);
        cudaFuncSetAttribute(gemm_i8<1, HID, DIM>,
                             cudaFuncAttributeMaxDynamicSharedMemorySize, SMEM_BYTES);
        attr_done = 1;
    }

    // quantize weights and F
    quant_w_k<<<1, 256>>>(wg1, W1d0, W1d1, W1d2, W1d3, qW1, DIM, HID);
    quant_w_k<<<4, 256>>>(wg2, W2d0, W2d1, W2d2, W2d3, qW2, HID, DIM);
    quant_f_k<<<BATCH, 256>>>(F);

    // GEMM1: H = relu(F @ Wg1 + bg1)
    gemm_i8<0, DIM, HID><<<dim3(HID / BN, BATCH / BM), 256, SMEM_BYTES>>>(
        Fd0, Fd1, Fd2, Fd3, W1d0, W1d1, W1d2, W1d3, qF, qW1, bg1, nullptr);
    // quantize H
    quant_h_k<<<BATCH, 256>>>();
    // GEMM2: comp = thresh(F * sigmoid(H @ Wg2 + bg2))
    gemm_i8<1, HID, DIM><<<dim3(DIM / BN, BATCH / BM), 256, SMEM_BYTES>>>(
        Hd0, Hd1, Hd2, Hd3, W2d0, W2d1, W2d2, W2d3, qH, qW2, bg2, F);
    // row-wise post-processing
    rowpost_k<<<BATCH / R3, 256>>>(wr1, br1, wr2, br2, wm1, bm1, wm2, bm2, out);
}

// round 17
// speedup vs baseline: 3.8821x; 3.8821x over previous
#include <cuda_runtime.h>
#include <cstdint>
#include <math.h>

#define BATCH 32768
#define DIM   1024
#define HID   256

typedef unsigned long long ull;

// ---------------- device scratch (no runtime allocation) -------------------
__device__ float g_H[(size_t)BATCH * HID];      // 32 MB

__device__ __forceinline__ float sigmoidf_(float x) {
    return 1.0f / (1.0f + expf(-x));
}

// packed fp32x2 FMA: each half is an independent IEEE-rn fp32 fma -> per-output
// accumulation chains bitwise identical to scalar fmaf (k ascending).
__device__ __forceinline__ void ffma2(ull& d, ull a, ull b) {
    asm("fma.rn.f32x2 %0, %1, %2, %0;" : "+l"(d) : "l"(a), "l"(b));
}
__device__ __forceinline__ ull pack2(float lo, float hi) {
    ull r;
    asm("mov.b64 %0, {%1, %2};" : "=l"(r) : "f"(lo), "f"(hi));
    return r;
}
__device__ __forceinline__ void unpack2(ull v, float& lo, float& hi) {
    asm("mov.b64 {%0, %1}, %2;" : "=f"(lo), "=f"(hi) : "l"(v));
}

__device__ __forceinline__ void cp16(void* s, const void* g) {
    uint32_t sa = (uint32_t)__cvta_generic_to_shared(s);
    asm volatile("cp.async.cg.shared.global [%0], [%1], 16;\n" :: "r"(sa), "l"(g));
}
#define CP_COMMIT() asm volatile("cp.async.commit_group;\n")
#define CP_WAIT0()  asm volatile("cp.async.wait_group 0;\n")

// ---------------------------------------------------------------------------
// GEMM1 (verbatim from R8, proven 328us / rel 2.1e-6):
// g_H = relu(F[32768,1024] @ Wg1[1024,256] + bg1)
// ---------------------------------------------------------------------------
#define BM 128
#define BN 128
#define BK 16
#define BM2 132
#define NT 256

struct Frag { float4 a0, a1, b0, b1; };

__global__ __launch_bounds__(NT, 2) void gemm1_k(
    const float* __restrict__ A,
    const float* __restrict__ W,
    const float* __restrict__ bias,
    float* __restrict__ C)
{
    constexpr int K = DIM, N = HID;
    constexpr int KT = K / BK;
    __shared__ float As[2][BK][BM2];
    __shared__ __align__(16) float Ws[2][BK][BN];

    const int tid   = threadIdx.x;
    const int lane  = tid & 31;
    const int wid   = tid >> 5;
    const int warpM = wid & 1;
    const int warpN = wid >> 1;
    const int lm8   = lane >> 2;
    const int ln4   = lane & 3;
    const int rA    = warpM * 64 + lm8 * 4;
    const int cB    = warpN * 32 + ln4 * 4;

    const int bx = blockIdx.x, by = blockIdx.y;
    const float* Ab = A + (size_t)by * BM * K;
    const float* Wb = W + (size_t)bx * BN;

    ull acc2[8][4];
#pragma unroll
    for (int i = 0; i < 8; i++)
#pragma unroll
        for (int j = 0; j < 4; j++) acc2[i][j] = pack2(0.0f, 0.0f);

    float4 Ar[2];
    auto ldgA = [&](int kt) {
#pragma unroll
        for (int u = 0; u < 2; u++) {
            int l = tid + u * NT, r = l >> 2, c4 = l & 3;
            Ar[u] = *(const float4*)(Ab + (size_t)r * K + kt * BK + c4 * 4);
        }
    };
    auto stsA = [&](int st) {
#pragma unroll
        for (int u = 0; u < 2; u++) {
            int l = tid + u * NT, r = l >> 2, c4 = l & 3;
            As[st][c4 * 4 + 0][r] = Ar[u].x;
            As[st][c4 * 4 + 1][r] = Ar[u].y;
            As[st][c4 * 4 + 2][r] = Ar[u].z;
            As[st][c4 * 4 + 3][r] = Ar[u].w;
        }
    };
    auto cpB = [&](int kt, int st) {
#pragma unroll
        for (int u = 0; u < 2; u++) {
            int l = tid + u * NT, kk = l >> 5, c16 = l & 31;
            cp16(&Ws[st][kk][c16 * 4],
                 Wb + (size_t)(kt * BK + kk) * N + c16 * 4);
        }
    };
    auto lds_frag = [&](Frag& f, int st, int k) {
        f.a0 = *(const float4*)&As[st][k][rA];
        f.a1 = *(const float4*)&As[st][k][rA + 32];
        f.b0 = *(const float4*)&Ws[st][k][cB];
        f.b1 = *(const float4*)&Ws[st][k][cB + 16];
    };
    auto fma_step = [&](const Frag& f) {
        ull bb[4] = { pack2(f.b0.x, f.b0.y), pack2(f.b0.z, f.b0.w),
                      pack2(f.b1.x, f.b1.y), pack2(f.b1.z, f.b1.w) };
        float av[8] = { f.a0.x, f.a0.y, f.a0.z, f.a0.w,
                        f.a1.x, f.a1.y, f.a1.z, f.a1.w };
#pragma unroll
        for (int i = 0; i < 8; i++) {
            ull ad = pack2(av[i], av[i]);
#pragma unroll
            for (int j = 0; j < 4; j++) ffma2(acc2[i][j], ad, bb[j]);
        }
    };

    ldgA(0);
    cpB(0, 0);
    CP_COMMIT();
    stsA(0);
    CP_WAIT0();
    __syncthreads();

    Frag fr[2];
    lds_frag(fr[0], 0, 0);

    for (int kt = 0; kt < KT; kt++) {
        const int st = kt & 1;
        if (kt + 1 < KT) { ldgA(kt + 1); cpB(kt + 1, st ^ 1); CP_COMMIT(); }
#pragma unroll
        for (int k = 0; k < BK; k++) {
            const int nb = (k + 1) & 1;
            if (k < BK - 1) {
                lds_frag(fr[nb], st, k + 1);
            } else if (kt + 1 < KT) {
                stsA(st ^ 1);
                CP_WAIT0();
                __syncthreads();
                lds_frag(fr[nb], st ^ 1, 0);
            }
            fma_step(fr[k & 1]);
        }
    }

#pragma unroll
    for (int i = 0; i < 8; i++) {
        size_t r = (size_t)by * BM + rA + (i >> 2) * 32 + (i & 3);
        float xv[8];
#pragma unroll
        for (int j = 0; j < 4; j++) unpack2(acc2[i][j], xv[2 * j], xv[2 * j + 1]);
#pragma unroll
        for (int gidx = 0; gidx < 2; gidx++) {
            int cbase = bx * BN + cB + gidx * 16;
            float4 res;
            res.x = fmaxf(xv[gidx * 4 + 0] + __ldg(bias + cbase + 0), 0.f);
            res.y = fmaxf(xv[gidx * 4 + 1] + __ldg(bias + cbase + 1), 0.f);
            res.z = fmaxf(xv[gidx * 4 + 2] + __ldg(bias + cbase + 2), 0.f);
            res.w = fmaxf(xv[gidx * 4 + 3] + __ldg(bias + cbase + 3), 0.f);
            *(float4*)(C + r * N + cbase) = res;
        }
    }
}

// ---------------------------------------------------------------------------
// Fused GEMM2 + rowpost: one CTA = 32 rows x full N=1024, K=256.
//   x = H @ Wg2 + bg2; gw = sigmoid(x); g = F*gw; comp = g>0.3?0:g
//   (reference "competition" branch is dead code: win == False always)
//   then full rowpost in-kernel; comp never leaves registers.
// 512 threads: 4 row-groups(8 rows) x 128 col-threads (cols c0..c0+3, c0+512..+3).
// ---------------------------------------------------------------------------
#define FKT 32          // 256 / 8
#define SM_AS   0                      // As[256][32] floats (A transposed)
#define SM_WS   8192                   // Ws[2][8][1024] floats (reused for w_r2)
#define SM_CNT  (8192 + 16384)         // [32][4]
#define SM_S1   (SM_CNT + 128)
#define SM_S2   (SM_S1 + 128)
#define SM_MX   (SM_S2 + 128)
#define SM_CSP  (SM_MX + 128)          // [32]
#define SM_THR  (SM_CSP + 32)          // [32]
#define FSMEM_FLOATS (SM_THR + 32)
#define FSMEM_BYTES  (FSMEM_FLOATS * 4)   // 100,608 B

__global__ __launch_bounds__(512, 1) void gemm2_fused_k(
    const float* __restrict__ W2,      // [256][1024]
    const float* __restrict__ bg2,
    const float* __restrict__ F,
    const float* __restrict__ w_r1, const float* __restrict__ b_r1,
    const float* __restrict__ w_r2, const float* __restrict__ b_r2,
    const float* __restrict__ w_m1, const float* __restrict__ b_m1,
    const float* __restrict__ w_m2, const float* __restrict__ b_m2,
    float* __restrict__ out)
{
    extern __shared__ __align__(16) float sm[];
    float* Asm = sm + SM_AS;      // [k][r]: k*32 + r
    float* Wsm = sm + SM_WS;      // stage st: (st*8+kk)*1024 + c  / later w_r2

    const int tid  = threadIdx.x;
    const int lane = tid & 31;
    const int g    = tid >> 7;          // row group 0..3
    const int wg   = (tid >> 5) & 3;    // warp within group
    const int lx   = tid & 127;
    const int c0   = lx * 4;            // cols c0..c0+3 and c0+512..c0+515
    const int r0   = g * 8;             // local rows r0..r0+7
    const size_t rBase = (size_t)blockIdx.x * 32;

    // ---- load A (g_H block) transposed into smem: As[k][r] ----
#pragma unroll
    for (int u = 0; u < 4; u++) {
        int l = tid + u * 512;
        int r = l >> 6, c4 = l & 63;
        float4 v = *(const float4*)(g_H + (rBase + r) * HID + c4 * 4);
        Asm[(c4 * 4 + 0) * 32 + r] = v.x;
        Asm[(c4 * 4 + 1) * 32 + r] = v.y;
        Asm[(c4 * 4 + 2) * 32 + r] = v.z;
        Asm[(c4 * 4 + 3) * 32 + r] = v.w;
    }

    // per stage: 8 k-rows x 1024 cols = 2048 float4 chunks; 512 thr x 4 iters.
    // kk = l >> 8 (0..7), c4 = l & 255 (0..255).   [R16 bug: >>7/&127 -> OOB]
    auto loadW = [&](int kt, int st) {
#pragma unroll
        for (int u = 0; u < 4; u++) {
            int l = tid + u * 512;
            int kk = l >> 8, c4 = l & 255;
            cp16(&Wsm[(st * 8 + kk) * 1024 + c4 * 4],
                 W2 + (size_t)(kt * 8 + kk) * 1024 + c4 * 4);
        }
    };

    loadW(0, 0);
    CP_COMMIT();
    CP_WAIT0();
    __syncthreads();

    ull acc2[8][4];
#pragma unroll
    for (int i = 0; i < 8; i++)
#pragma unroll
        for (int j = 0; j < 4; j++) acc2[i][j] = pack2(0.0f, 0.0f);

    for (int kt = 0; kt < FKT; kt++) {
        const int st = kt & 1;
        if (kt + 1 < FKT) { loadW(kt + 1, st ^ 1); CP_COMMIT(); }
#pragma unroll
        for (int kk = 0; kk < 8; kk++) {
            int k = kt * 8 + kk;
            float4 a0 = *(const float4*)&Asm[k * 32 + r0];
            float4 a1 = *(const float4*)&Asm[k * 32 + r0 + 4];
            float4 b0 = *(const float4*)&Wsm[(st * 8 + kk) * 1024 + c0];
            float4 b1 = *(const float4*)&Wsm[(st * 8 + kk) * 1024 + c0 + 512];
            ull bb[4] = { pack2(b0.x, b0.y), pack2(b0.z, b0.w),
                          pack2(b1.x, b1.y), pack2(b1.z, b1.w) };
            float av[8] = { a0.x, a0.y, a0.z, a0.w, a1.x, a1.y, a1.z, a1.w };
#pragma unroll
            for (int i = 0; i < 8; i++) {
                ull ad = pack2(av[i], av[i]);
#pragma unroll
                for (int j = 0; j < 4; j++) ffma2(acc2[i][j], ad, bb[j]);
            }
        }
        if (kt + 1 < FKT) { CP_WAIT0(); __syncthreads(); }
    }

    // ---- epilogue: comp in registers ----
    float comp[8][8];
    {
        float bb0[4], bb1[4];
#pragma unroll
        for (int j = 0; j < 4; j++) {
            bb0[j] = __ldg(bg2 + c0 + j);
            bb1[j] = __ldg(bg2 + c0 + 512 + j);
        }
#pragma unroll
        for (int i = 0; i < 8; i++) {
            float xv[8];
#pragma unroll
            for (int j = 0; j < 4; j++) unpack2(acc2[i][j], xv[2 * j], xv[2 * j + 1]);
            size_t row = rBase + r0 + i;
            float4 f0 = *(const float4*)(F + row * DIM + c0);
            float4 f1 = *(const float4*)(F + row * DIM + c0 + 512);
            float fv[8] = { f0.x, f0.y, f0.z, f0.w, f1.x, f1.y, f1.z, f1.w };
#pragma unroll
            for (int j = 0; j < 8; j++) {
                float x = xv[j] + ((j < 4) ? bb0[j] : bb1[j - 4]);
                float gv = fv[j] * sigmoidf_(x);
                comp[i][j] = (gv > 0.3f) ? 0.0f : gv;   // win == False always
            }
        }
    }

    // ---- reuse Wsm for w_r2 (all cp.async drained; barrier protects WAR) ----
    __syncthreads();
#pragma unroll
    for (int u = 0; u < 8; u++) {
        int l = tid + u * 512;
        int k = l >> 8, c4 = l & 255;
        *(float4*)&Wsm[k * 1024 + c4 * 4] = *(const float4*)(w_r2 + k * 1024 + c4 * 4);
    }

    // ---- round 1: cur_sp counts (integer-exact in fp32) ----
#pragma unroll
    for (int i = 0; i < 8; i++) {
        float cnt = 0.0f;
#pragma unroll
        for (int j = 0; j < 8; j++) cnt += (fabsf(comp[i][j]) < 0.1f) ? 1.0f : 0.0f;
#pragma unroll
        for (int o = 16; o; o >>= 1) cnt += __shfl_xor_sync(0xffffffffu, cnt, o);
        if (lane == 0) sm[SM_CNT + (r0 + i) * 4 + wg] = cnt;
    }
    __syncthreads();
    if (tid < 32) {
        float s = sm[SM_CNT + tid * 4 + 0] + sm[SM_CNT + tid * 4 + 1]
                + sm[SM_CNT + tid * 4 + 2] + sm[SM_CNT + tid * 4 + 3];
        sm[SM_CSP + tid] = s * (1.0f / 1024.0f);
    }
    __syncthreads();

    // ---- round 2: rw, dyn (overwrite comp), row stats ----
#pragma unroll
    for (int i = 0; i < 8; i++) {
        float cs = sm[SM_CSP + r0 + i];
        float hr[16];
#pragma unroll
        for (int k = 0; k < 16; k++) {
            float x = fmaf(cs, __ldg(w_r1 + k),
                      fmaf(0.1f, __ldg(w_r1 + 16 + k), __ldg(b_r1 + k)));
            hr[k] = fmaxf(x, 0.0f);
        }
        float s1 = 0.0f, s2 = 0.0f, mx = -INFINITY;
#pragma unroll
        for (int j = 0; j < 8; j++) {
            int col = (j < 4) ? (c0 + j) : (c0 + 512 + j - 4);
            float a = __ldg(b_r2 + col);
#pragma unroll
            for (int k = 0; k < 16; k++) a = fmaf(hr[k], Wsm[k * 1024 + col], a);
            float rw = sigmoidf_(a);
            float d = comp[i][j] * rw;
            comp[i][j] = d;
            s1 += d;
            s2 = fmaf(d, d, s2);
            mx = fmaxf(mx, d);
        }
#pragma unroll
        for (int o = 16; o; o >>= 1) {
            s1 += __shfl_xor_sync(0xffffffffu, s1, o);
            s2 += __shfl_xor_sync(0xffffffffu, s2, o);
            mx = fmaxf(mx, __shfl_xor_sync(0xffffffffu, mx, o));
        }
        if (lane == 0) {
            sm[SM_S1 + (r0 + i) * 4 + wg] = s1;
            sm[SM_S2 + (r0 + i) * 4 + wg] = s2;
            sm[SM_MX + (r0 + i) * 4 + wg] = mx;
        }
    }
    __syncthreads();

    // ---- per-row threshold ----
    if (tid < 32) {
        float s1 = 0.0f, s2 = 0.0f, mx = -INFINITY;
#pragma unroll
        for (int w = 0; w < 4; w++) {
            s1 += sm[SM_S1 + tid * 4 + w];
            s2 += sm[SM_S2 + tid * 4 + w];
            mx = fmaxf(mx, sm[SM_MX + tid * 4 + w]);
        }
        float fmean = s1 * (1.0f / 1024.0f);
        float var = fmaxf((s2 - s1 * fmean) * (1.0f / 1023.0f), 0.0f);  // ddof=1
        float fstd = sqrtf(var);
        float a2 = __ldg(b_m2);
#pragma unroll
        for (int k = 0; k < 16; k++) {
            float x = fmaf(fmean, __ldg(w_m1 + k),
                      fmaf(fstd, __ldg(w_m1 + 16 + k),
                      fmaf(mx,   __ldg(w_m1 + 32 + k), __ldg(b_m1 + k))));
            a2 = fmaf(fmaxf(x, 0.0f), __ldg(w_m2 + k), a2);
        }
        sm[SM_THR + tid] = sigmoidf_(a2);
    }
    __syncthreads();

    // ---- final mask + write ----
#pragma unroll
    for (int i = 0; i < 8; i++) {
        float thr = sm[SM_THR + r0 + i];
        size_t row = rBase + r0 + i;
        float4 o0, o1;
        o0.x = (fabsf(comp[i][0]) > thr) ? comp[i][0] : 0.0f;
        o0.y = (fabsf(comp[i][1]) > thr) ? comp[i][1] : 0.0f;
        o0.z = (fabsf(comp[i][2]) > thr) ? comp[i][2] : 0.0f;
        o0.w = (fabsf(comp[i][3]) > thr) ? comp[i][3] : 0.0f;
        o1.x = (fabsf(comp[i][4]) > thr) ? comp[i][4] : 0.0f;
        o1.y = (fabsf(comp[i][5]) > thr) ? comp[i][5] : 0.0f;
        o1.z = (fabsf(comp[i][6]) > thr) ? comp[i][6] : 0.0f;
        o1.w = (fabsf(comp[i][7]) > thr) ? comp[i][7] : 0.0f;
        *(float4*)(out + row * DIM + c0) = o0;
        *(float4*)(out + row * DIM + c0 + 512) = o1;
    }
}

// ---------------------------------------------------------------------------
// Launch
// ---------------------------------------------------------------------------
extern "C" void kernel_launch(void* const* d_in, const int* in_sizes, int n_in,
                              void* d_out, int out_size)
{
    const float* F   = (const float*)d_in[0];
    const float* wg1 = (const float*)d_in[1];
    const float* bg1 = (const float*)d_in[2];
    const float* wg2 = (const float*)d_in[3];
    const float* bg2 = (const float*)d_in[4];
    // d_in[5..8] = competition weights: dead code (win == False always)
    const float* wr1 = (const float*)d_in[9];
    const float* br1 = (const float*)d_in[10];
    const float* wr2 = (const float*)d_in[11];
    const float* br2 = (const float*)d_in[12];
    const float* wm1 = (const float*)d_in[13];
    const float* bm1 = (const float*)d_in[14];
    const float* wm2 = (const float*)d_in[15];
    const float* bm2 = (const float*)d_in[16];
    float* out = (float*)d_out;
    (void)in_sizes; (void)n_in; (void)out_size;

    float* H;
    cudaGetSymbolAddress((void**)&H, g_H);

    static int attr_done = 0;
    if (!attr_done) {
        cudaFuncSetAttribute(gemm2_fused_k,
                             cudaFuncAttributeMaxDynamicSharedMemorySize, FSMEM_BYTES);
        attr_done = 1;
    }

    // GEMM1: H = relu(F @ Wg1 + bg1)      [32768 x 256], K=1024
    gemm1_k<<<dim3(HID / BN, BATCH / BM), NT>>>(F, wg1, bg1, H);
    // fused GEMM2 + rowpost -> out
    gemm2_fused_k<<<BATCH / 32, 512, FSMEM_BYTES>>>(
        wg2, bg2, F, wr1, br1, wr2, br2, wm1, bm1, wm2, bm2, out);
}